// round 5
// baseline (speedup 1.0000x reference)
#include <cuda_runtime.h>
#include <cuda_fp16.h>
#include <cstdint>
#include <cstddef>

#define NN 50000
#define NE 800000
#define DI 256
#define DO 256
#define NR 8

// fp16 scratch: xt[r][n][o]  (204.8 MB)
__device__ __half g_xt[(size_t)NR * NN * DO];
// tf32-pre-rounded copies of x and W
__device__ float g_xr[(size_t)NN * DI];
__device__ float g_wr[(size_t)NR * DI * DO];
// CSR-by-destination scaffolding
__device__ int g_cnt[NN];
__device__ int g_offs[NN + 1];
__device__ int g_curs[NN];
__device__ uint32_t g_perm[NE];     // packed payload: col | (rel<<16)

__device__ __forceinline__ float f2tf32(float f) {
    uint32_t u;
    asm("cvt.rna.tf32.f32 %0, %1;" : "=r"(u) : "f"(f));
    return __uint_as_float(u);
}
__device__ __forceinline__ void cp_async16(uint32_t saddr, const void* gaddr) {
    asm volatile("cp.async.cg.shared.global [%0], [%1], 16;" :: "r"(saddr), "l"(gaddr));
}
__device__ __forceinline__ void cp_async16_pred(uint32_t saddr, const void* gaddr, int sz) {
    asm volatile("cp.async.cg.shared.global [%0], [%1], 16, %2;"
                 :: "r"(saddr), "l"(gaddr), "r"(sz));
}
__device__ __forceinline__ uint32_t smem_u32(const void* p) {
    uint32_t a;
    asm("{ .reg .u64 t; cvta.to.shared.u64 t, %1; cvt.u32.u64 %0, t; }" : "=r"(a) : "l"(p));
    return a;
}

// ---------------------------------------------------------------------------
// tf32 pre-round (rna), float4-vectorized
// ---------------------------------------------------------------------------
__global__ void rgcn_round(const float4* __restrict__ src, float4* __restrict__ dst, int n4) {
    int i = blockIdx.x * blockDim.x + threadIdx.x;
    if (i >= n4) return;
    float4 v = src[i];
    v.x = f2tf32(v.x); v.y = f2tf32(v.y); v.z = f2tf32(v.z); v.w = f2tf32(v.w);
    dst[i] = v;
}

// ---------------------------------------------------------------------------
// CSR build: count -> scan (1 block) -> fill perm
// ---------------------------------------------------------------------------
__global__ void rgcn_count(const int* __restrict__ edge_index, int* __restrict__ cnt) {
    int e = blockIdx.x * blockDim.x + threadIdx.x;
    if (e < NE) atomicAdd(&cnt[edge_index[e]], 1);
}
__global__ __launch_bounds__(1024)
void rgcn_scan(const int* __restrict__ cnt, int* __restrict__ offs, int* __restrict__ curs) {
    __shared__ int ssum[1024];
    const int t = threadIdx.x;
    const int PER = (NN + 1023) / 1024;      // 49
    const int base = t * PER;
    int s = 0;
    for (int k = 0; k < PER; k++) {
        int i = base + k;
        if (i < NN) s += cnt[i];
    }
    ssum[t] = s;
    __syncthreads();
    for (int d = 1; d < 1024; d <<= 1) {
        int v = (t >= d) ? ssum[t - d] : 0;
        __syncthreads();
        ssum[t] += v;
        __syncthreads();
    }
    int run = ssum[t] - s;                   // exclusive prefix
    for (int k = 0; k < PER; k++) {
        int i = base + k;
        if (i < NN) {
            offs[i] = run;
            curs[i] = run;
            run += cnt[i];
        }
    }
    if (t == 1023) offs[NN] = ssum[1023];
}
__global__ void rgcn_fill(const int* __restrict__ edge_index,
                          const int* __restrict__ edge_type,
                          int* __restrict__ curs, uint32_t* __restrict__ perm) {
    int e = blockIdx.x * blockDim.x + threadIdx.x;
    if (e >= NE) return;
    int row = edge_index[e];
    int col = edge_index[NE + e];
    int r   = edge_type[e];
    int pos = atomicAdd(&curs[row], 1);
    perm[pos] = (uint32_t)col | ((uint32_t)r << 16);
}

// ---------------------------------------------------------------------------
// GEMM: xt[r] = x @ W[r], fp16 out. tf32 mma m16n8k8.
// CTA: 128 threads (4 warps, 2x2), tile 128x128, warp tile 64x64.
// BK=32, 2-stage cp.async double buffer, 3 CTAs/SM.
// ---------------------------------------------------------------------------
#define BK 32
#define NCH (DI / BK)                 // 8
#define A_PITCH 36
#define B_PITCH 136
#define A_WORDS (128 * A_PITCH)
#define B_WORDS (BK * B_PITCH)
#define STAGE_WORDS (A_WORDS + B_WORDS)
#define SMEM_DYN (2 * STAGE_WORDS * 4)

__global__ __launch_bounds__(128, 3)
void rgcn_gemm(const float* __restrict__ x, const float* __restrict__ w,
               __half* __restrict__ xt) {
    extern __shared__ float smem[];

    const int r  = blockIdx.z;
    const int m0 = blockIdx.x * 128;
    const int n0 = blockIdx.y * 128;

    const int tid  = threadIdx.x;
    const int lane = tid & 31;
    const int wid  = tid >> 5;
    const int wm   = wid & 1;     // m half (64)
    const int wn   = wid >> 1;    // n half (64)
    const int g    = lane >> 2;
    const int t    = lane & 3;

    const uint32_t sbase = smem_u32(smem);
    const float* wr = w + (size_t)r * DI * DO;

    float c[4][8][4];
#pragma unroll
    for (int mi = 0; mi < 4; mi++)
#pragma unroll
        for (int ni = 0; ni < 8; ni++)
#pragma unroll
            for (int q = 0; q < 4; q++) c[mi][ni][q] = 0.0f;

    auto load_chunk = [&](int ci, int stage) {
        const int kt = ci * BK;
        const uint32_t sA = sbase + stage * STAGE_WORDS * 4;
        const uint32_t sB = sA + A_WORDS * 4;
#pragma unroll
        for (int u = 0; u < 8; u++) {
            int v = tid + u * 128;            // A: 1024 f4 = 128 rows x 8
            int row = v >> 3, c4 = v & 7;
            int gm = m0 + row;
            uint32_t sa = sA + (row * A_PITCH + c4 * 4) * 4;
            cp_async16_pred(sa, x + (size_t)gm * DI + kt + c4 * 4, (gm < NN) ? 16 : 0);
        }
#pragma unroll
        for (int u = 0; u < 8; u++) {
            int v = tid + u * 128;            // B: 1024 f4 = 32 rows x 32
            int row = v >> 5, c4 = v & 31;
            uint32_t sb = sB + (row * B_PITCH + c4 * 4) * 4;
            cp_async16(sb, wr + (size_t)(kt + row) * DO + n0 + c4 * 4);
        }
        asm volatile("cp.async.commit_group;" ::: "memory");
    };

    load_chunk(0, 0);

#pragma unroll
    for (int i = 0; i < NCH; i++) {
        if (i + 1 < NCH) {
            load_chunk(i + 1, (i + 1) & 1);
            asm volatile("cp.async.wait_group 1;" ::: "memory");
        } else {
            asm volatile("cp.async.wait_group 0;" ::: "memory");
        }
        __syncthreads();

        const float* As = smem + (i & 1) * STAGE_WORDS;
        const float* Bs = As + A_WORDS;

#pragma unroll
        for (int kk = 0; kk < 4; kk++) {
            const int k8 = kk * 8;
            uint32_t a[4][4];
#pragma unroll
            for (int mi = 0; mi < 4; mi++) {
                int row = wm * 64 + mi * 16 + g;
                a[mi][0] = __float_as_uint(As[row * A_PITCH + k8 + t]);
                a[mi][1] = __float_as_uint(As[(row + 8) * A_PITCH + k8 + t]);
                a[mi][2] = __float_as_uint(As[row * A_PITCH + k8 + t + 4]);
                a[mi][3] = __float_as_uint(As[(row + 8) * A_PITCH + k8 + t + 4]);
            }
#pragma unroll
            for (int ni = 0; ni < 8; ni++) {
                int col = wn * 64 + ni * 8 + g;
                uint32_t b0 = __float_as_uint(Bs[(k8 + t) * B_PITCH + col]);
                uint32_t b1 = __float_as_uint(Bs[(k8 + t + 4) * B_PITCH + col]);
#pragma unroll
                for (int mi = 0; mi < 4; mi++) {
                    asm volatile(
                        "mma.sync.aligned.m16n8k8.row.col.f32.tf32.tf32.f32 "
                        "{%0,%1,%2,%3}, {%4,%5,%6,%7}, {%8,%9}, {%0,%1,%2,%3};\n"
                        : "+f"(c[mi][ni][0]), "+f"(c[mi][ni][1]),
                          "+f"(c[mi][ni][2]), "+f"(c[mi][ni][3])
                        : "r"(a[mi][0]), "r"(a[mi][1]), "r"(a[mi][2]), "r"(a[mi][3]),
                          "r"(b0), "r"(b1));
                }
            }
        }
        __syncthreads();
    }

    __half* xtr = xt + (size_t)r * NN * DO;
#pragma unroll
    for (int mi = 0; mi < 4; mi++) {
#pragma unroll
        for (int ni = 0; ni < 8; ni++) {
            int row0 = m0 + wm * 64 + mi * 16 + g;
            int col  = n0 + wn * 64 + ni * 8 + t * 2;
            if (row0 < NN)
                *(half2*)(xtr + (size_t)row0 * DO + col) =
                    __float22half2_rn(make_float2(c[mi][ni][0], c[mi][ni][1]));
            int row1 = row0 + 8;
            if (row1 < NN)
                *(half2*)(xtr + (size_t)row1 * DO + col) =
                    __float22half2_rn(make_float2(c[mi][ni][2], c[mi][ni][3]));
        }
    }
}

// ---------------------------------------------------------------------------
// Aggregate: one warp per destination node, 4-deep LDG.128 pipeline,
// register accumulation, fused bias+relu.
// ---------------------------------------------------------------------------
__device__ __forceinline__ void acc_vec(float* acc, const uint4& v) {
    float2 f;
    f = __half22float2(*(const half2*)&v.x); acc[0] += f.x; acc[1] += f.y;
    f = __half22float2(*(const half2*)&v.y); acc[2] += f.x; acc[3] += f.y;
    f = __half22float2(*(const half2*)&v.z); acc[4] += f.x; acc[5] += f.y;
    f = __half22float2(*(const half2*)&v.w); acc[6] += f.x; acc[7] += f.y;
}

__global__ __launch_bounds__(256)
void rgcn_aggregate(const __half* __restrict__ xt,
                    const float* __restrict__ bias,
                    const int* __restrict__ offs,
                    const uint32_t* __restrict__ perm,
                    float* __restrict__ out) {
    const int n = blockIdx.x * 8 + (threadIdx.x >> 5);
    if (n >= NN) return;
    const int lane = threadIdx.x & 31;

    const int s = offs[n];
    const int e = offs[n + 1];

    float acc[8];
#pragma unroll
    for (int k = 0; k < 8; k++) acc[k] = 0.0f;

    int j = s;
    for (; j + 3 < e; j += 4) {
        uint32_t p0 = perm[j], p1 = perm[j + 1], p2 = perm[j + 2], p3 = perm[j + 3];
        uint4 v0 = __ldg((const uint4*)(xt +
            (((size_t)(p0 >> 16)) * NN + (size_t)(p0 & 0xFFFFu)) * DO) + lane);
        uint4 v1 = __ldg((const uint4*)(xt +
            (((size_t)(p1 >> 16)) * NN + (size_t)(p1 & 0xFFFFu)) * DO) + lane);
        uint4 v2 = __ldg((const uint4*)(xt +
            (((size_t)(p2 >> 16)) * NN + (size_t)(p2 & 0xFFFFu)) * DO) + lane);
        uint4 v3 = __ldg((const uint4*)(xt +
            (((size_t)(p3 >> 16)) * NN + (size_t)(p3 & 0xFFFFu)) * DO) + lane);
        acc_vec(acc, v0); acc_vec(acc, v1); acc_vec(acc, v2); acc_vec(acc, v3);
    }
    for (; j < e; j++) {
        uint32_t p0 = perm[j];
        uint4 v0 = __ldg((const uint4*)(xt +
            (((size_t)(p0 >> 16)) * NN + (size_t)(p0 & 0xFFFFu)) * DO) + lane);
        acc_vec(acc, v0);
    }

    const float4 b0 = *(const float4*)(bias + lane * 8);
    const float4 b1 = *(const float4*)(bias + lane * 8 + 4);
    float4 o0, o1;
    o0.x = fmaxf(acc[0] + b0.x, 0.f); o0.y = fmaxf(acc[1] + b0.y, 0.f);
    o0.z = fmaxf(acc[2] + b0.z, 0.f); o0.w = fmaxf(acc[3] + b0.w, 0.f);
    o1.x = fmaxf(acc[4] + b1.x, 0.f); o1.y = fmaxf(acc[5] + b1.y, 0.f);
    o1.z = fmaxf(acc[6] + b1.z, 0.f); o1.w = fmaxf(acc[7] + b1.w, 0.f);

    float* dst = out + (size_t)n * DO + lane * 8;
    *(float4*)dst = o0;
    *(float4*)(dst + 4) = o1;
}

extern "C" void kernel_launch(void* const* d_in, const int* in_sizes, int n_in,
                              void* d_out, int out_size) {
    const float* x          = (const float*)d_in[0];
    const int*   edge_index = (const int*)d_in[1];
    const int*   edge_type  = (const int*)d_in[2];
    const float* weight     = (const float*)d_in[3];
    const float* bias       = (const float*)d_in[4];
    float* out = (float*)d_out;

    float *xr, *wr;
    __half* xt;
    int *cnt, *offs, *curs;
    uint32_t* perm;
    cudaGetSymbolAddress((void**)&xr, g_xr);
    cudaGetSymbolAddress((void**)&wr, g_wr);
    cudaGetSymbolAddress((void**)&xt, g_xt);
    cudaGetSymbolAddress((void**)&cnt, g_cnt);
    cudaGetSymbolAddress((void**)&offs, g_offs);
    cudaGetSymbolAddress((void**)&curs, g_curs);
    cudaGetSymbolAddress((void**)&perm, g_perm);

    cudaFuncSetAttribute(rgcn_gemm, cudaFuncAttributeMaxDynamicSharedMemorySize, SMEM_DYN);

    const int xn4 = NN * DI / 4;
    const int wn4 = NR * DI * DO / 4;
    rgcn_round<<<(xn4 + 255) / 256, 256>>>((const float4*)x, (float4*)xr, xn4);
    rgcn_round<<<(wn4 + 255) / 256, 256>>>((const float4*)weight, (float4*)wr, wn4);

    // CSR build
    cudaMemsetAsync(cnt, 0, NN * sizeof(int));
    rgcn_count<<<(NE + 255) / 256, 256>>>(edge_index, cnt);
    rgcn_scan<<<1, 1024>>>(cnt, offs, curs);
    rgcn_fill<<<(NE + 255) / 256, 256>>>(edge_index, edge_type, curs, perm);

    dim3 gg((NN + 127) / 128, DO / 128, NR);     // 391 x 2 x 8
    rgcn_gemm<<<gg, 128, SMEM_DYN>>>(xr, wr, xt);

    rgcn_aggregate<<<(NN + 7) / 8, 256>>>(xt, bias, offs, perm, out);
}

// round 6
// speedup vs baseline: 1.6490x; 1.6490x over previous
#include <cuda_runtime.h>
#include <cuda_fp16.h>
#include <cstdint>
#include <cstddef>

#define NN 50000
#define NE 800000
#define DI 256
#define DO 256
#define NR 8

#define NBLK ((NN + 255) / 256)   // 196 scan blocks

// fp16 scratch: xt[r][n][o]  (204.8 MB)
__device__ __half g_xt[(size_t)NR * NN * DO];
// tf32-pre-rounded copies of x and W
__device__ float g_xr[(size_t)NN * DI];
__device__ float g_wr[(size_t)NR * DI * DO];
// CSR-by-destination scaffolding
__device__ int g_cnt[NN];
__device__ int g_offs[NN + 1];
__device__ int g_curs[NN];
__device__ int g_bsum[NBLK];
__device__ int g_bbase[NBLK];
__device__ uint32_t g_perm[NE];     // packed payload: col | (rel<<16)

__device__ __forceinline__ float f2tf32(float f) {
    uint32_t u;
    asm("cvt.rna.tf32.f32 %0, %1;" : "=r"(u) : "f"(f));
    return __uint_as_float(u);
}
__device__ __forceinline__ void cp_async16(uint32_t saddr, const void* gaddr) {
    asm volatile("cp.async.cg.shared.global [%0], [%1], 16;" :: "r"(saddr), "l"(gaddr));
}
__device__ __forceinline__ void cp_async16_pred(uint32_t saddr, const void* gaddr, int sz) {
    asm volatile("cp.async.cg.shared.global [%0], [%1], 16, %2;"
                 :: "r"(saddr), "l"(gaddr), "r"(sz));
}
__device__ __forceinline__ uint32_t smem_u32(const void* p) {
    uint32_t a;
    asm("{ .reg .u64 t; cvta.to.shared.u64 t, %1; cvt.u32.u64 %0, t; }" : "=r"(a) : "l"(p));
    return a;
}

// ---------------------------------------------------------------------------
// tf32 pre-round (rna), float4-vectorized
// ---------------------------------------------------------------------------
__global__ void rgcn_round(const float4* __restrict__ src, float4* __restrict__ dst, int n4) {
    int i = blockIdx.x * blockDim.x + threadIdx.x;
    if (i >= n4) return;
    float4 v = src[i];
    v.x = f2tf32(v.x); v.y = f2tf32(v.y); v.z = f2tf32(v.z); v.w = f2tf32(v.w);
    dst[i] = v;
}

// ---------------------------------------------------------------------------
// CSR build: count -> 3-phase parallel scan -> fill perm
// ---------------------------------------------------------------------------
__global__ void rgcn_count(const int* __restrict__ edge_index, int* __restrict__ cnt) {
    int e = blockIdx.x * blockDim.x + threadIdx.x;
    if (e < NE) atomicAdd(&cnt[edge_index[e]], 1);
}

// Phase A: per-block (256 nodes) exclusive scan; block total to bsum.
__global__ __launch_bounds__(256)
void rgcn_scanA(const int* __restrict__ cnt, int* __restrict__ offs, int* __restrict__ bsum) {
    __shared__ int s[256];
    const int t = threadIdx.x;
    const int i = blockIdx.x * 256 + t;
    int v = (i < NN) ? cnt[i] : 0;
    s[t] = v;
    __syncthreads();
#pragma unroll
    for (int d = 1; d < 256; d <<= 1) {
        int u = (t >= d) ? s[t - d] : 0;
        __syncthreads();
        s[t] += u;
        __syncthreads();
    }
    if (i < NN) offs[i] = s[t] - v;          // local exclusive
    if (t == 255) bsum[blockIdx.x] = s[255];
}

// Phase B: single block scans NBLK block sums (exclusive).
__global__ __launch_bounds__(256)
void rgcn_scanB(const int* __restrict__ bsum, int* __restrict__ bbase) {
    __shared__ int s[256];
    const int t = threadIdx.x;
    int v = (t < NBLK) ? bsum[t] : 0;
    s[t] = v;
    __syncthreads();
#pragma unroll
    for (int d = 1; d < 256; d <<= 1) {
        int u = (t >= d) ? s[t - d] : 0;
        __syncthreads();
        s[t] += u;
        __syncthreads();
    }
    if (t < NBLK) bbase[t] = s[t] - v;       // exclusive
}

// Phase C: add block base, produce final offs + curs.
__global__ __launch_bounds__(256)
void rgcn_scanC(int* __restrict__ offs, const int* __restrict__ bbase,
                int* __restrict__ curs) {
    const int i = blockIdx.x * 256 + threadIdx.x;
    if (i >= NN) return;
    int o = offs[i] + bbase[blockIdx.x];
    offs[i] = o;
    curs[i] = o;
    if (i == 0) offs[NN] = NE;
}

__global__ void rgcn_fill(const int* __restrict__ edge_index,
                          const int* __restrict__ edge_type,
                          int* __restrict__ curs, uint32_t* __restrict__ perm) {
    int e = blockIdx.x * blockDim.x + threadIdx.x;
    if (e >= NE) return;
    int row = edge_index[e];
    int col = edge_index[NE + e];
    int r   = edge_type[e];
    int pos = atomicAdd(&curs[row], 1);
    perm[pos] = (uint32_t)col | ((uint32_t)r << 16);
}

// ---------------------------------------------------------------------------
// GEMM: xt[r] = x @ W[r], fp16 out. tf32 mma m16n8k8.
// CTA: 128 threads (4 warps, 2x2), tile 128x128, warp tile 64x64.
// BK=32, 2-stage cp.async double buffer, 2 CTAs/SM (3 spills registers!).
// ---------------------------------------------------------------------------
#define BK 32
#define NCH (DI / BK)                 // 8
#define A_PITCH 36
#define B_PITCH 136
#define A_WORDS (128 * A_PITCH)
#define B_WORDS (BK * B_PITCH)
#define STAGE_WORDS (A_WORDS + B_WORDS)
#define SMEM_DYN (2 * STAGE_WORDS * 4)

__global__ __launch_bounds__(128, 2)
void rgcn_gemm(const float* __restrict__ x, const float* __restrict__ w,
               __half* __restrict__ xt) {
    extern __shared__ float smem[];

    const int r  = blockIdx.z;
    const int m0 = blockIdx.x * 128;
    const int n0 = blockIdx.y * 128;

    const int tid  = threadIdx.x;
    const int lane = tid & 31;
    const int wid  = tid >> 5;
    const int wm   = wid & 1;     // m half (64)
    const int wn   = wid >> 1;    // n half (64)
    const int g    = lane >> 2;
    const int t    = lane & 3;

    const uint32_t sbase = smem_u32(smem);
    const float* wr = w + (size_t)r * DI * DO;

    float c[4][8][4];
#pragma unroll
    for (int mi = 0; mi < 4; mi++)
#pragma unroll
        for (int ni = 0; ni < 8; ni++)
#pragma unroll
            for (int q = 0; q < 4; q++) c[mi][ni][q] = 0.0f;

    auto load_chunk = [&](int ci, int stage) {
        const int kt = ci * BK;
        const uint32_t sA = sbase + stage * STAGE_WORDS * 4;
        const uint32_t sB = sA + A_WORDS * 4;
#pragma unroll
        for (int u = 0; u < 8; u++) {
            int v = tid + u * 128;            // A: 1024 f4 = 128 rows x 8
            int row = v >> 3, c4 = v & 7;
            int gm = m0 + row;
            uint32_t sa = sA + (row * A_PITCH + c4 * 4) * 4;
            cp_async16_pred(sa, x + (size_t)gm * DI + kt + c4 * 4, (gm < NN) ? 16 : 0);
        }
#pragma unroll
        for (int u = 0; u < 8; u++) {
            int v = tid + u * 128;            // B: 1024 f4 = 32 rows x 32
            int row = v >> 5, c4 = v & 31;
            uint32_t sb = sB + (row * B_PITCH + c4 * 4) * 4;
            cp_async16(sb, wr + (size_t)(kt + row) * DO + n0 + c4 * 4);
        }
        asm volatile("cp.async.commit_group;" ::: "memory");
    };

    load_chunk(0, 0);

#pragma unroll
    for (int i = 0; i < NCH; i++) {
        if (i + 1 < NCH) {
            load_chunk(i + 1, (i + 1) & 1);
            asm volatile("cp.async.wait_group 1;" ::: "memory");
        } else {
            asm volatile("cp.async.wait_group 0;" ::: "memory");
        }
        __syncthreads();

        const float* As = smem + (i & 1) * STAGE_WORDS;
        const float* Bs = As + A_WORDS;

#pragma unroll
        for (int kk = 0; kk < 4; kk++) {
            const int k8 = kk * 8;
            uint32_t a[4][4];
#pragma unroll
            for (int mi = 0; mi < 4; mi++) {
                int row = wm * 64 + mi * 16 + g;
                a[mi][0] = __float_as_uint(As[row * A_PITCH + k8 + t]);
                a[mi][1] = __float_as_uint(As[(row + 8) * A_PITCH + k8 + t]);
                a[mi][2] = __float_as_uint(As[row * A_PITCH + k8 + t + 4]);
                a[mi][3] = __float_as_uint(As[(row + 8) * A_PITCH + k8 + t + 4]);
            }
#pragma unroll
            for (int ni = 0; ni < 8; ni++) {
                int col = wn * 64 + ni * 8 + g;
                uint32_t b0 = __float_as_uint(Bs[(k8 + t) * B_PITCH + col]);
                uint32_t b1 = __float_as_uint(Bs[(k8 + t + 4) * B_PITCH + col]);
#pragma unroll
                for (int mi = 0; mi < 4; mi++) {
                    asm volatile(
                        "mma.sync.aligned.m16n8k8.row.col.f32.tf32.tf32.f32 "
                        "{%0,%1,%2,%3}, {%4,%5,%6,%7}, {%8,%9}, {%0,%1,%2,%3};\n"
                        : "+f"(c[mi][ni][0]), "+f"(c[mi][ni][1]),
                          "+f"(c[mi][ni][2]), "+f"(c[mi][ni][3])
                        : "r"(a[mi][0]), "r"(a[mi][1]), "r"(a[mi][2]), "r"(a[mi][3]),
                          "r"(b0), "r"(b1));
                }
            }
        }
        __syncthreads();
    }

    __half* xtr = xt + (size_t)r * NN * DO;
#pragma unroll
    for (int mi = 0; mi < 4; mi++) {
#pragma unroll
        for (int ni = 0; ni < 8; ni++) {
            int row0 = m0 + wm * 64 + mi * 16 + g;
            int col  = n0 + wn * 64 + ni * 8 + t * 2;
            if (row0 < NN)
                *(half2*)(xtr + (size_t)row0 * DO + col) =
                    __float22half2_rn(make_float2(c[mi][ni][0], c[mi][ni][1]));
            int row1 = row0 + 8;
            if (row1 < NN)
                *(half2*)(xtr + (size_t)row1 * DO + col) =
                    __float22half2_rn(make_float2(c[mi][ni][2], c[mi][ni][3]));
        }
    }
}

// ---------------------------------------------------------------------------
// Aggregate: one warp per destination node, 4-deep LDG.128 pipeline,
// register accumulation, fused bias+relu.
// ---------------------------------------------------------------------------
__device__ __forceinline__ void acc_vec(float* acc, const uint4& v) {
    float2 f;
    f = __half22float2(*(const half2*)&v.x); acc[0] += f.x; acc[1] += f.y;
    f = __half22float2(*(const half2*)&v.y); acc[2] += f.x; acc[3] += f.y;
    f = __half22float2(*(const half2*)&v.z); acc[4] += f.x; acc[5] += f.y;
    f = __half22float2(*(const half2*)&v.w); acc[6] += f.x; acc[7] += f.y;
}

__global__ __launch_bounds__(256)
void rgcn_aggregate(const __half* __restrict__ xt,
                    const float* __restrict__ bias,
                    const int* __restrict__ offs,
                    const uint32_t* __restrict__ perm,
                    float* __restrict__ out) {
    const int n = blockIdx.x * 8 + (threadIdx.x >> 5);
    if (n >= NN) return;
    const int lane = threadIdx.x & 31;

    const int s = offs[n];
    const int e = offs[n + 1];

    float acc[8];
#pragma unroll
    for (int k = 0; k < 8; k++) acc[k] = 0.0f;

    int j = s;
    for (; j + 3 < e; j += 4) {
        uint32_t p0 = perm[j], p1 = perm[j + 1], p2 = perm[j + 2], p3 = perm[j + 3];
        uint4 v0 = __ldg((const uint4*)(xt +
            (((size_t)(p0 >> 16)) * NN + (size_t)(p0 & 0xFFFFu)) * DO) + lane);
        uint4 v1 = __ldg((const uint4*)(xt +
            (((size_t)(p1 >> 16)) * NN + (size_t)(p1 & 0xFFFFu)) * DO) + lane);
        uint4 v2 = __ldg((const uint4*)(xt +
            (((size_t)(p2 >> 16)) * NN + (size_t)(p2 & 0xFFFFu)) * DO) + lane);
        uint4 v3 = __ldg((const uint4*)(xt +
            (((size_t)(p3 >> 16)) * NN + (size_t)(p3 & 0xFFFFu)) * DO) + lane);
        acc_vec(acc, v0); acc_vec(acc, v1); acc_vec(acc, v2); acc_vec(acc, v3);
    }
    for (; j < e; j++) {
        uint32_t p0 = perm[j];
        uint4 v0 = __ldg((const uint4*)(xt +
            (((size_t)(p0 >> 16)) * NN + (size_t)(p0 & 0xFFFFu)) * DO) + lane);
        acc_vec(acc, v0);
    }

    const float4 b0 = *(const float4*)(bias + lane * 8);
    const float4 b1 = *(const float4*)(bias + lane * 8 + 4);
    float4 o0, o1;
    o0.x = fmaxf(acc[0] + b0.x, 0.f); o0.y = fmaxf(acc[1] + b0.y, 0.f);
    o0.z = fmaxf(acc[2] + b0.z, 0.f); o0.w = fmaxf(acc[3] + b0.w, 0.f);
    o1.x = fmaxf(acc[4] + b1.x, 0.f); o1.y = fmaxf(acc[5] + b1.y, 0.f);
    o1.z = fmaxf(acc[6] + b1.z, 0.f); o1.w = fmaxf(acc[7] + b1.w, 0.f);

    float* dst = out + (size_t)n * DO + lane * 8;
    *(float4*)dst = o0;
    *(float4*)(dst + 4) = o1;
}

extern "C" void kernel_launch(void* const* d_in, const int* in_sizes, int n_in,
                              void* d_out, int out_size) {
    const float* x          = (const float*)d_in[0];
    const int*   edge_index = (const int*)d_in[1];
    const int*   edge_type  = (const int*)d_in[2];
    const float* weight     = (const float*)d_in[3];
    const float* bias       = (const float*)d_in[4];
    float* out = (float*)d_out;

    float *xr, *wr;
    __half* xt;
    int *cnt, *offs, *curs, *bsum, *bbase;
    uint32_t* perm;
    cudaGetSymbolAddress((void**)&xr, g_xr);
    cudaGetSymbolAddress((void**)&wr, g_wr);
    cudaGetSymbolAddress((void**)&xt, g_xt);
    cudaGetSymbolAddress((void**)&cnt, g_cnt);
    cudaGetSymbolAddress((void**)&offs, g_offs);
    cudaGetSymbolAddress((void**)&curs, g_curs);
    cudaGetSymbolAddress((void**)&bsum, g_bsum);
    cudaGetSymbolAddress((void**)&bbase, g_bbase);
    cudaGetSymbolAddress((void**)&perm, g_perm);

    cudaFuncSetAttribute(rgcn_gemm, cudaFuncAttributeMaxDynamicSharedMemorySize, SMEM_DYN);

    const int xn4 = NN * DI / 4;
    const int wn4 = NR * DI * DO / 4;
    rgcn_round<<<(xn4 + 255) / 256, 256>>>((const float4*)x, (float4*)xr, xn4);
    rgcn_round<<<(wn4 + 255) / 256, 256>>>((const float4*)weight, (float4*)wr, wn4);

    // CSR build
    cudaMemsetAsync(cnt, 0, NN * sizeof(int));
    rgcn_count<<<(NE + 255) / 256, 256>>>(edge_index, cnt);
    rgcn_scanA<<<NBLK, 256>>>(cnt, offs, bsum);
    rgcn_scanB<<<1, 256>>>(bsum, bbase);
    rgcn_scanC<<<NBLK, 256>>>(offs, bbase, curs);
    rgcn_fill<<<(NE + 255) / 256, 256>>>(edge_index, edge_type, curs, perm);

    dim3 gg((NN + 127) / 128, DO / 128, NR);     // 391 x 2 x 8
    rgcn_gemm<<<gg, 128, SMEM_DYN>>>(xr, wr, xt);

    rgcn_aggregate<<<(NN + 7) / 8, 256>>>(xt, bias, offs, perm, out);
}

// round 7
// speedup vs baseline: 1.6787x; 1.0180x over previous
#include <cuda_runtime.h>
#include <cuda_fp16.h>
#include <cstdint>
#include <cstddef>

#define NN 50000
#define NE 800000
#define DI 256
#define DO 256
#define NR 8

#define NBLK ((NN + 255) / 256)   // 196 scan blocks

// fp16 scratch: xt[r][n][o]  (204.8 MB)
__device__ __half g_xt[(size_t)NR * NN * DO];
// tf32-pre-rounded copies of x and W
__device__ float g_xr[(size_t)NN * DI];
__device__ float g_wr[(size_t)NR * DI * DO];
// CSR-by-destination scaffolding
__device__ int g_cnt[NN];
__device__ int g_offs[NN + 1];
__device__ int g_curs[NN];
__device__ int g_bsum[NBLK];
__device__ int g_bbase[NBLK];
__device__ uint32_t g_perm[NE];     // packed payload: col | (rel<<16)

__device__ __forceinline__ float f2tf32(float f) {
    uint32_t u;
    asm("cvt.rna.tf32.f32 %0, %1;" : "=r"(u) : "f"(f));
    return __uint_as_float(u);
}
__device__ __forceinline__ void cp_async16(uint32_t saddr, const void* gaddr) {
    asm volatile("cp.async.cg.shared.global [%0], [%1], 16;" :: "r"(saddr), "l"(gaddr));
}
__device__ __forceinline__ void cp_async16_pred(uint32_t saddr, const void* gaddr, int sz) {
    asm volatile("cp.async.cg.shared.global [%0], [%1], 16, %2;"
                 :: "r"(saddr), "l"(gaddr), "r"(sz));
}
__device__ __forceinline__ uint32_t smem_u32(const void* p) {
    uint32_t a;
    asm("{ .reg .u64 t; cvta.to.shared.u64 t, %1; cvt.u32.u64 %0, t; }" : "=r"(a) : "l"(p));
    return a;
}

// ---------------------------------------------------------------------------
// tf32 pre-round (rna), float4-vectorized
// ---------------------------------------------------------------------------
__global__ void rgcn_round(const float4* __restrict__ src, float4* __restrict__ dst, int n4) {
    int i = blockIdx.x * blockDim.x + threadIdx.x;
    if (i >= n4) return;
    float4 v = src[i];
    v.x = f2tf32(v.x); v.y = f2tf32(v.y); v.z = f2tf32(v.z); v.w = f2tf32(v.w);
    dst[i] = v;
}

// ---------------------------------------------------------------------------
// CSR build: count -> 3-phase parallel scan -> fill perm
// ---------------------------------------------------------------------------
__global__ void rgcn_count(const int* __restrict__ edge_index, int* __restrict__ cnt) {
    int e = blockIdx.x * blockDim.x + threadIdx.x;
    if (e < NE) atomicAdd(&cnt[edge_index[e]], 1);
}

__global__ __launch_bounds__(256)
void rgcn_scanA(const int* __restrict__ cnt, int* __restrict__ offs, int* __restrict__ bsum) {
    __shared__ int s[256];
    const int t = threadIdx.x;
    const int i = blockIdx.x * 256 + t;
    int v = (i < NN) ? cnt[i] : 0;
    s[t] = v;
    __syncthreads();
#pragma unroll
    for (int d = 1; d < 256; d <<= 1) {
        int u = (t >= d) ? s[t - d] : 0;
        __syncthreads();
        s[t] += u;
        __syncthreads();
    }
    if (i < NN) offs[i] = s[t] - v;
    if (t == 255) bsum[blockIdx.x] = s[255];
}

__global__ __launch_bounds__(256)
void rgcn_scanB(const int* __restrict__ bsum, int* __restrict__ bbase) {
    __shared__ int s[256];
    const int t = threadIdx.x;
    int v = (t < NBLK) ? bsum[t] : 0;
    s[t] = v;
    __syncthreads();
#pragma unroll
    for (int d = 1; d < 256; d <<= 1) {
        int u = (t >= d) ? s[t - d] : 0;
        __syncthreads();
        s[t] += u;
        __syncthreads();
    }
    if (t < NBLK) bbase[t] = s[t] - v;
}

__global__ __launch_bounds__(256)
void rgcn_scanC(int* __restrict__ offs, const int* __restrict__ bbase,
                int* __restrict__ curs) {
    const int i = blockIdx.x * 256 + threadIdx.x;
    if (i >= NN) return;
    int o = offs[i] + bbase[blockIdx.x];
    offs[i] = o;
    curs[i] = o;
    if (i == 0) offs[NN] = NE;
}

__global__ void rgcn_fill(const int* __restrict__ edge_index,
                          const int* __restrict__ edge_type,
                          int* __restrict__ curs, uint32_t* __restrict__ perm) {
    int e = blockIdx.x * blockDim.x + threadIdx.x;
    if (e >= NE) return;
    int row = edge_index[e];
    int col = edge_index[NE + e];
    int r   = edge_type[e];
    int pos = atomicAdd(&curs[row], 1);
    perm[pos] = (uint32_t)col | ((uint32_t)r << 16);
}

// ---------------------------------------------------------------------------
// GEMM: xt[r] = x @ W[r], fp16 out. tf32 mma m16n8k8.
// CTA: 128 threads (4 warps, 2x2), tile 128x128, warp tile 64x64.
// BK=32, 3-stage cp.async pipeline (107.5 KB smem), 2 CTAs/SM.
// ---------------------------------------------------------------------------
#define BK 32
#define NCH (DI / BK)                 // 8
#define NSTAGE 3
#define A_PITCH 36
#define B_PITCH 136
#define A_WORDS (128 * A_PITCH)
#define B_WORDS (BK * B_PITCH)
#define STAGE_WORDS (A_WORDS + B_WORDS)
#define SMEM_DYN (NSTAGE * STAGE_WORDS * 4)

__global__ __launch_bounds__(128, 2)
void rgcn_gemm(const float* __restrict__ x, const float* __restrict__ w,
               __half* __restrict__ xt) {
    extern __shared__ float smem[];

    const int r  = blockIdx.z;
    const int m0 = blockIdx.x * 128;
    const int n0 = blockIdx.y * 128;

    const int tid  = threadIdx.x;
    const int lane = tid & 31;
    const int wid  = tid >> 5;
    const int wm   = wid & 1;
    const int wn   = wid >> 1;
    const int g    = lane >> 2;
    const int t    = lane & 3;

    const uint32_t sbase = smem_u32(smem);
    const float* wr = w + (size_t)r * DI * DO;

    float c[4][8][4];
#pragma unroll
    for (int mi = 0; mi < 4; mi++)
#pragma unroll
        for (int ni = 0; ni < 8; ni++)
#pragma unroll
            for (int q = 0; q < 4; q++) c[mi][ni][q] = 0.0f;

    auto load_chunk = [&](int ci, int stage) {
        const int kt = ci * BK;
        const uint32_t sA = sbase + stage * STAGE_WORDS * 4;
        const uint32_t sB = sA + A_WORDS * 4;
#pragma unroll
        for (int u = 0; u < 8; u++) {
            int v = tid + u * 128;            // A: 1024 f4 = 128 rows x 8
            int row = v >> 3, c4 = v & 7;
            int gm = m0 + row;
            uint32_t sa = sA + (row * A_PITCH + c4 * 4) * 4;
            cp_async16_pred(sa, x + (size_t)gm * DI + kt + c4 * 4, (gm < NN) ? 16 : 0);
        }
#pragma unroll
        for (int u = 0; u < 8; u++) {
            int v = tid + u * 128;            // B: 1024 f4 = 32 rows x 32
            int row = v >> 5, c4 = v & 31;
            uint32_t sb = sB + (row * B_PITCH + c4 * 4) * 4;
            cp_async16(sb, wr + (size_t)(kt + row) * DO + n0 + c4 * 4);
        }
        asm volatile("cp.async.commit_group;" ::: "memory");
    };

    load_chunk(0, 0);
    load_chunk(1, 1);

#pragma unroll
    for (int i = 0; i < NCH; i++) {
        if (i + 2 < NCH) load_chunk(i + 2, (i + 2) % NSTAGE);
        if (i + 2 < NCH)      asm volatile("cp.async.wait_group 2;" ::: "memory");
        else if (i + 1 < NCH) asm volatile("cp.async.wait_group 1;" ::: "memory");
        else                  asm volatile("cp.async.wait_group 0;" ::: "memory");
        __syncthreads();

        const float* As = smem + (i % NSTAGE) * STAGE_WORDS;
        const float* Bs = As + A_WORDS;

#pragma unroll
        for (int kk = 0; kk < 4; kk++) {
            const int k8 = kk * 8;
            uint32_t a[4][4];
#pragma unroll
            for (int mi = 0; mi < 4; mi++) {
                int row = wm * 64 + mi * 16 + g;
                a[mi][0] = __float_as_uint(As[row * A_PITCH + k8 + t]);
                a[mi][1] = __float_as_uint(As[(row + 8) * A_PITCH + k8 + t]);
                a[mi][2] = __float_as_uint(As[row * A_PITCH + k8 + t + 4]);
                a[mi][3] = __float_as_uint(As[(row + 8) * A_PITCH + k8 + t + 4]);
            }
#pragma unroll
            for (int ni = 0; ni < 8; ni++) {
                int col = wn * 64 + ni * 8 + g;
                uint32_t b0 = __float_as_uint(Bs[(k8 + t) * B_PITCH + col]);
                uint32_t b1 = __float_as_uint(Bs[(k8 + t + 4) * B_PITCH + col]);
#pragma unroll
                for (int mi = 0; mi < 4; mi++) {
                    asm volatile(
                        "mma.sync.aligned.m16n8k8.row.col.f32.tf32.tf32.f32 "
                        "{%0,%1,%2,%3}, {%4,%5,%6,%7}, {%8,%9}, {%0,%1,%2,%3};\n"
                        : "+f"(c[mi][ni][0]), "+f"(c[mi][ni][1]),
                          "+f"(c[mi][ni][2]), "+f"(c[mi][ni][3])
                        : "r"(a[mi][0]), "r"(a[mi][1]), "r"(a[mi][2]), "r"(a[mi][3]),
                          "r"(b0), "r"(b1));
                }
            }
        }
        __syncthreads();
    }

    __half* xtr = xt + (size_t)r * NN * DO;
#pragma unroll
    for (int mi = 0; mi < 4; mi++) {
#pragma unroll
        for (int ni = 0; ni < 8; ni++) {
            int row0 = m0 + wm * 64 + mi * 16 + g;
            int col  = n0 + wn * 64 + ni * 8 + t * 2;
            if (row0 < NN)
                *(half2*)(xtr + (size_t)row0 * DO + col) =
                    __float22half2_rn(make_float2(c[mi][ni][0], c[mi][ni][1]));
            int row1 = row0 + 8;
            if (row1 < NN)
                *(half2*)(xtr + (size_t)row1 * DO + col) =
                    __float22half2_rn(make_float2(c[mi][ni][2], c[mi][ni][3]));
        }
    }
}

// ---------------------------------------------------------------------------
// Aggregate: one warp per destination node, 4-deep LDG.128 pipeline,
// register accumulation, fused bias+relu.
// ---------------------------------------------------------------------------
__device__ __forceinline__ void acc_vec(float* acc, const uint4& v) {
    float2 f;
    f = __half22float2(*(const half2*)&v.x); acc[0] += f.x; acc[1] += f.y;
    f = __half22float2(*(const half2*)&v.y); acc[2] += f.x; acc[3] += f.y;
    f = __half22float2(*(const half2*)&v.z); acc[4] += f.x; acc[5] += f.y;
    f = __half22float2(*(const half2*)&v.w); acc[6] += f.x; acc[7] += f.y;
}

__global__ __launch_bounds__(256)
void rgcn_aggregate(const __half* __restrict__ xt,
                    const float* __restrict__ bias,
                    const int* __restrict__ offs,
                    const uint32_t* __restrict__ perm,
                    float* __restrict__ out) {
    const int n = blockIdx.x * 8 + (threadIdx.x >> 5);
    if (n >= NN) return;
    const int lane = threadIdx.x & 31;

    const int s = offs[n];
    const int e = offs[n + 1];

    float acc[8];
#pragma unroll
    for (int k = 0; k < 8; k++) acc[k] = 0.0f;

    int j = s;
    for (; j + 3 < e; j += 4) {
        uint32_t p0 = perm[j], p1 = perm[j + 1], p2 = perm[j + 2], p3 = perm[j + 3];
        uint4 v0 = __ldg((const uint4*)(xt +
            (((size_t)(p0 >> 16)) * NN + (size_t)(p0 & 0xFFFFu)) * DO) + lane);
        uint4 v1 = __ldg((const uint4*)(xt +
            (((size_t)(p1 >> 16)) * NN + (size_t)(p1 & 0xFFFFu)) * DO) + lane);
        uint4 v2 = __ldg((const uint4*)(xt +
            (((size_t)(p2 >> 16)) * NN + (size_t)(p2 & 0xFFFFu)) * DO) + lane);
        uint4 v3 = __ldg((const uint4*)(xt +
            (((size_t)(p3 >> 16)) * NN + (size_t)(p3 & 0xFFFFu)) * DO) + lane);
        acc_vec(acc, v0); acc_vec(acc, v1); acc_vec(acc, v2); acc_vec(acc, v3);
    }
    for (; j < e; j++) {
        uint32_t p0 = perm[j];
        uint4 v0 = __ldg((const uint4*)(xt +
            (((size_t)(p0 >> 16)) * NN + (size_t)(p0 & 0xFFFFu)) * DO) + lane);
        acc_vec(acc, v0);
    }

    const float4 b0 = *(const float4*)(bias + lane * 8);
    const float4 b1 = *(const float4*)(bias + lane * 8 + 4);
    float4 o0, o1;
    o0.x = fmaxf(acc[0] + b0.x, 0.f); o0.y = fmaxf(acc[1] + b0.y, 0.f);
    o0.z = fmaxf(acc[2] + b0.z, 0.f); o0.w = fmaxf(acc[3] + b0.w, 0.f);
    o1.x = fmaxf(acc[4] + b1.x, 0.f); o1.y = fmaxf(acc[5] + b1.y, 0.f);
    o1.z = fmaxf(acc[6] + b1.z, 0.f); o1.w = fmaxf(acc[7] + b1.w, 0.f);

    float* dst = out + (size_t)n * DO + lane * 8;
    *(float4*)dst = o0;
    *(float4*)(dst + 4) = o1;
}

extern "C" void kernel_launch(void* const* d_in, const int* in_sizes, int n_in,
                              void* d_out, int out_size) {
    const float* x          = (const float*)d_in[0];
    const int*   edge_index = (const int*)d_in[1];
    const int*   edge_type  = (const int*)d_in[2];
    const float* weight     = (const float*)d_in[3];
    const float* bias       = (const float*)d_in[4];
    float* out = (float*)d_out;

    float *xr, *wr;
    __half* xt;
    int *cnt, *offs, *curs, *bsum, *bbase;
    uint32_t* perm;
    cudaGetSymbolAddress((void**)&xr, g_xr);
    cudaGetSymbolAddress((void**)&wr, g_wr);
    cudaGetSymbolAddress((void**)&xt, g_xt);
    cudaGetSymbolAddress((void**)&cnt, g_cnt);
    cudaGetSymbolAddress((void**)&offs, g_offs);
    cudaGetSymbolAddress((void**)&curs, g_curs);
    cudaGetSymbolAddress((void**)&bsum, g_bsum);
    cudaGetSymbolAddress((void**)&bbase, g_bbase);
    cudaGetSymbolAddress((void**)&perm, g_perm);

    cudaFuncSetAttribute(rgcn_gemm, cudaFuncAttributeMaxDynamicSharedMemorySize, SMEM_DYN);

    const int xn4 = NN * DI / 4;
    const int wn4 = NR * DI * DO / 4;
    rgcn_round<<<(xn4 + 255) / 256, 256>>>((const float4*)x, (float4*)xr, xn4);
    rgcn_round<<<(wn4 + 255) / 256, 256>>>((const float4*)weight, (float4*)wr, wn4);

    // CSR build
    cudaMemsetAsync(cnt, 0, NN * sizeof(int));
    rgcn_count<<<(NE + 255) / 256, 256>>>(edge_index, cnt);
    rgcn_scanA<<<NBLK, 256>>>(cnt, offs, bsum);
    rgcn_scanB<<<1, 256>>>(bsum, bbase);
    rgcn_scanC<<<NBLK, 256>>>(offs, bbase, curs);
    rgcn_fill<<<(NE + 255) / 256, 256>>>(edge_index, edge_type, curs, perm);

    dim3 gg((NN + 127) / 128, DO / 128, NR);     // 391 x 2 x 8
    rgcn_gemm<<<gg, 128, SMEM_DYN>>>(xr, wr, xt);

    rgcn_aggregate<<<(NN + 7) / 8, 256>>>(xt, bias, offs, perm, out);
}

// round 8
// speedup vs baseline: 2.6883x; 1.6014x over previous
#include <cuda_runtime.h>
#include <cuda_fp16.h>
#include <cstdint>
#include <cstddef>

#define NN 50000
#define NE 800000
#define DI 256
#define DO 256
#define NR 8

#define NBLK ((NN + 255) / 256)   // 196 scan blocks

// fp16 scratch: xt[r][n][o]  (204.8 MB)
__device__ __half g_xt[(size_t)NR * NN * DO];
// fp16 copies of x and W
__device__ __half g_xh[(size_t)NN * DI];      // 25.6 MB
__device__ __half g_wh[(size_t)NR * DI * DO]; // 1 MB
// CSR-by-destination scaffolding
__device__ int g_cnt[NN];
__device__ int g_offs[NN + 1];
__device__ int g_curs[NN];
__device__ int g_bsum[NBLK];
__device__ int g_bbase[NBLK];
__device__ uint32_t g_perm[NE];     // packed payload: col | (rel<<16)

__device__ __forceinline__ void cp_async16(uint32_t saddr, const void* gaddr) {
    asm volatile("cp.async.cg.shared.global [%0], [%1], 16;" :: "r"(saddr), "l"(gaddr));
}
__device__ __forceinline__ void cp_async16_pred(uint32_t saddr, const void* gaddr, int sz) {
    asm volatile("cp.async.cg.shared.global [%0], [%1], 16, %2;"
                 :: "r"(saddr), "l"(gaddr), "r"(sz));
}
__device__ __forceinline__ uint32_t smem_u32(const void* p) {
    uint32_t a;
    asm("{ .reg .u64 t; cvta.to.shared.u64 t, %1; cvt.u32.u64 %0, t; }" : "=r"(a) : "l"(p));
    return a;
}
__device__ __forceinline__ void ldsm_x4(uint32_t* r, uint32_t addr) {
    asm volatile("ldmatrix.sync.aligned.m8n8.x4.shared.b16 {%0,%1,%2,%3}, [%4];"
                 : "=r"(r[0]), "=r"(r[1]), "=r"(r[2]), "=r"(r[3]) : "r"(addr));
}
__device__ __forceinline__ void ldsm_x4_t(uint32_t* r, uint32_t addr) {
    asm volatile("ldmatrix.sync.aligned.m8n8.x4.trans.shared.b16 {%0,%1,%2,%3}, [%4];"
                 : "=r"(r[0]), "=r"(r[1]), "=r"(r[2]), "=r"(r[3]) : "r"(addr));
}

// ---------------------------------------------------------------------------
// fp32 -> fp16 convert, float4-vectorized (8 B out per thread)
// ---------------------------------------------------------------------------
__global__ void rgcn_tohalf(const float4* __restrict__ src, half2* __restrict__ dst, int n4) {
    int i = blockIdx.x * blockDim.x + threadIdx.x;
    if (i >= n4) return;
    float4 v = src[i];
    dst[2 * i]     = __floats2half2_rn(v.x, v.y);
    dst[2 * i + 1] = __floats2half2_rn(v.z, v.w);
}

// ---------------------------------------------------------------------------
// CSR build: count -> 3-phase parallel scan -> fill perm
// ---------------------------------------------------------------------------
__global__ void rgcn_count(const int* __restrict__ edge_index, int* __restrict__ cnt) {
    int e = blockIdx.x * blockDim.x + threadIdx.x;
    if (e < NE) atomicAdd(&cnt[edge_index[e]], 1);
}

__global__ __launch_bounds__(256)
void rgcn_scanA(const int* __restrict__ cnt, int* __restrict__ offs, int* __restrict__ bsum) {
    __shared__ int s[256];
    const int t = threadIdx.x;
    const int i = blockIdx.x * 256 + t;
    int v = (i < NN) ? cnt[i] : 0;
    s[t] = v;
    __syncthreads();
#pragma unroll
    for (int d = 1; d < 256; d <<= 1) {
        int u = (t >= d) ? s[t - d] : 0;
        __syncthreads();
        s[t] += u;
        __syncthreads();
    }
    if (i < NN) offs[i] = s[t] - v;
    if (t == 255) bsum[blockIdx.x] = s[255];
}

__global__ __launch_bounds__(256)
void rgcn_scanB(const int* __restrict__ bsum, int* __restrict__ bbase) {
    __shared__ int s[256];
    const int t = threadIdx.x;
    int v = (t < NBLK) ? bsum[t] : 0;
    s[t] = v;
    __syncthreads();
#pragma unroll
    for (int d = 1; d < 256; d <<= 1) {
        int u = (t >= d) ? s[t - d] : 0;
        __syncthreads();
        s[t] += u;
        __syncthreads();
    }
    if (t < NBLK) bbase[t] = s[t] - v;
}

__global__ __launch_bounds__(256)
void rgcn_scanC(int* __restrict__ offs, const int* __restrict__ bbase,
                int* __restrict__ curs) {
    const int i = blockIdx.x * 256 + threadIdx.x;
    if (i >= NN) return;
    int o = offs[i] + bbase[blockIdx.x];
    offs[i] = o;
    curs[i] = o;
    if (i == 0) offs[NN] = NE;
}

__global__ void rgcn_fill(const int* __restrict__ edge_index,
                          const int* __restrict__ edge_type,
                          int* __restrict__ curs, uint32_t* __restrict__ perm) {
    int e = blockIdx.x * blockDim.x + threadIdx.x;
    if (e >= NE) return;
    int row = edge_index[e];
    int col = edge_index[NE + e];
    int r   = edge_type[e];
    int pos = atomicAdd(&curs[row], 1);
    perm[pos] = (uint32_t)col | ((uint32_t)r << 16);
}

// ---------------------------------------------------------------------------
// GEMM: xt[r] = x @ W[r], fp16 in/out, fp32 accum. mma m16n8k16.
// CTA: 128 threads (4 warps, 2x2), tile 128x128, warp tile 64x64.
// BK=64, 3-stage cp.async pipeline, ldmatrix fragment loads, 2 CTAs/SM.
// ---------------------------------------------------------------------------
#define BK 64
#define NCH (DI / BK)                 // 4
#define NSTAGE 3
#define APH 72                        // A pitch (halves): rows hit all 32 banks
#define BPH 136                       // B pitch (halves)
#define A_BYTES (128 * APH * 2)       // 18432
#define B_BYTES (BK * BPH * 2)        // 17408
#define STAGE_BYTES (A_BYTES + B_BYTES)
#define SMEM_DYN (NSTAGE * STAGE_BYTES)

__global__ __launch_bounds__(128, 2)
void rgcn_gemm(const __half* __restrict__ x, const __half* __restrict__ w,
               __half* __restrict__ xt) {
    extern __shared__ char smem[];

    const int r  = blockIdx.z;
    const int m0 = blockIdx.x * 128;
    const int n0 = blockIdx.y * 128;

    const int tid  = threadIdx.x;
    const int lane = tid & 31;
    const int wid  = tid >> 5;
    const int wm   = wid & 1;
    const int wn   = wid >> 1;
    const int g    = lane >> 2;
    const int t    = lane & 3;

    const uint32_t sbase = smem_u32(smem);
    const __half* wr = w + (size_t)r * DI * DO;

    float c[4][8][4];
#pragma unroll
    for (int mi = 0; mi < 4; mi++)
#pragma unroll
        for (int ni = 0; ni < 8; ni++)
#pragma unroll
            for (int q = 0; q < 4; q++) c[mi][ni][q] = 0.0f;

    auto load_chunk = [&](int ci, int stage) {
        const int kt = ci * BK;
        const uint32_t sA = sbase + stage * STAGE_BYTES;
        const uint32_t sB = sA + A_BYTES;
#pragma unroll
        for (int u = 0; u < 8; u++) {
            int v = tid + u * 128;            // A: 1024 lines = 128 rows x 8
            int row = v >> 3, kq = v & 7;
            int gm = m0 + row;
            uint32_t sa = sA + (row * APH + kq * 8) * 2;
            cp_async16_pred(sa, x + (size_t)gm * DI + kt + kq * 8, (gm < NN) ? 16 : 0);
        }
#pragma unroll
        for (int u = 0; u < 8; u++) {
            int v = tid + u * 128;            // B: 1024 lines = 64 rows x 16
            int row = v >> 4, c8 = v & 15;
            uint32_t sb = sB + (row * BPH + c8 * 8) * 2;
            cp_async16(sb, wr + (size_t)(kt + row) * DO + n0 + c8 * 8);
        }
        asm volatile("cp.async.commit_group;" ::: "memory");
    };

    load_chunk(0, 0);
    load_chunk(1, 1);

    // lane-dependent ldmatrix address components
    const int a_row = wm * 64 + (lane & 15);          // + mi*16
    const int a_kof = (lane >> 4) * 8;                // + k16
    const int b_krow = (lane & 7) + ((lane >> 3) & 1) * 8;   // + k16
    const int b_col  = wn * 64 + (lane >> 4) * 8;     // + p*16

#pragma unroll
    for (int i = 0; i < NCH; i++) {
        if (i + 2 < NCH) load_chunk(i + 2, (i + 2) % NSTAGE);
        if (i + 2 < NCH)      asm volatile("cp.async.wait_group 2;" ::: "memory");
        else if (i + 1 < NCH) asm volatile("cp.async.wait_group 1;" ::: "memory");
        else                  asm volatile("cp.async.wait_group 0;" ::: "memory");
        __syncthreads();

        const uint32_t sA = sbase + (i % NSTAGE) * STAGE_BYTES;
        const uint32_t sB = sA + A_BYTES;

#pragma unroll
        for (int s = 0; s < 4; s++) {         // 4 x k16 steps
            const int k16 = s * 16;
            uint32_t a[4][4];
#pragma unroll
            for (int mi = 0; mi < 4; mi++)
                ldsm_x4(a[mi], sA + ((a_row + mi * 16) * APH + k16 + a_kof) * 2);
            uint32_t b[4][4];
#pragma unroll
            for (int p = 0; p < 4; p++)
                ldsm_x4_t(b[p], sB + ((k16 + b_krow) * BPH + b_col + p * 16) * 2);
#pragma unroll
            for (int p = 0; p < 4; p++) {
#pragma unroll
                for (int mi = 0; mi < 4; mi++) {
                    asm volatile(
                        "mma.sync.aligned.m16n8k16.row.col.f32.f16.f16.f32 "
                        "{%0,%1,%2,%3}, {%4,%5,%6,%7}, {%8,%9}, {%0,%1,%2,%3};\n"
                        : "+f"(c[mi][2 * p][0]), "+f"(c[mi][2 * p][1]),
                          "+f"(c[mi][2 * p][2]), "+f"(c[mi][2 * p][3])
                        : "r"(a[mi][0]), "r"(a[mi][1]), "r"(a[mi][2]), "r"(a[mi][3]),
                          "r"(b[p][0]), "r"(b[p][1]));
                    asm volatile(
                        "mma.sync.aligned.m16n8k16.row.col.f32.f16.f16.f32 "
                        "{%0,%1,%2,%3}, {%4,%5,%6,%7}, {%8,%9}, {%0,%1,%2,%3};\n"
                        : "+f"(c[mi][2 * p + 1][0]), "+f"(c[mi][2 * p + 1][1]),
                          "+f"(c[mi][2 * p + 1][2]), "+f"(c[mi][2 * p + 1][3])
                        : "r"(a[mi][0]), "r"(a[mi][1]), "r"(a[mi][2]), "r"(a[mi][3]),
                          "r"(b[p][2]), "r"(b[p][3]));
                }
            }
        }
        __syncthreads();
    }

    __half* xtr = xt + (size_t)r * NN * DO;
#pragma unroll
    for (int mi = 0; mi < 4; mi++) {
#pragma unroll
        for (int ni = 0; ni < 8; ni++) {
            int row0 = m0 + wm * 64 + mi * 16 + g;
            int col  = n0 + wn * 64 + ni * 8 + t * 2;
            if (row0 < NN)
                *(half2*)(xtr + (size_t)row0 * DO + col) =
                    __float22half2_rn(make_float2(c[mi][ni][0], c[mi][ni][1]));
            int row1 = row0 + 8;
            if (row1 < NN)
                *(half2*)(xtr + (size_t)row1 * DO + col) =
                    __float22half2_rn(make_float2(c[mi][ni][2], c[mi][ni][3]));
        }
    }
}

// ---------------------------------------------------------------------------
// Aggregate: one warp per destination node, 4-deep LDG.128 pipeline,
// register accumulation, fused bias+relu.
// ---------------------------------------------------------------------------
__device__ __forceinline__ void acc_vec(float* acc, const uint4& v) {
    float2 f;
    f = __half22float2(*(const half2*)&v.x); acc[0] += f.x; acc[1] += f.y;
    f = __half22float2(*(const half2*)&v.y); acc[2] += f.x; acc[3] += f.y;
    f = __half22float2(*(const half2*)&v.z); acc[4] += f.x; acc[5] += f.y;
    f = __half22float2(*(const half2*)&v.w); acc[6] += f.x; acc[7] += f.y;
}

__global__ __launch_bounds__(256)
void rgcn_aggregate(const __half* __restrict__ xt,
                    const float* __restrict__ bias,
                    const int* __restrict__ offs,
                    const uint32_t* __restrict__ perm,
                    float* __restrict__ out) {
    const int n = blockIdx.x * 8 + (threadIdx.x >> 5);
    if (n >= NN) return;
    const int lane = threadIdx.x & 31;

    const int s = offs[n];
    const int e = offs[n + 1];

    float acc[8];
#pragma unroll
    for (int k = 0; k < 8; k++) acc[k] = 0.0f;

    int j = s;
    for (; j + 3 < e; j += 4) {
        uint32_t p0 = perm[j], p1 = perm[j + 1], p2 = perm[j + 2], p3 = perm[j + 3];
        uint4 v0 = __ldg((const uint4*)(xt +
            (((size_t)(p0 >> 16)) * NN + (size_t)(p0 & 0xFFFFu)) * DO) + lane);
        uint4 v1 = __ldg((const uint4*)(xt +
            (((size_t)(p1 >> 16)) * NN + (size_t)(p1 & 0xFFFFu)) * DO) + lane);
        uint4 v2 = __ldg((const uint4*)(xt +
            (((size_t)(p2 >> 16)) * NN + (size_t)(p2 & 0xFFFFu)) * DO) + lane);
        uint4 v3 = __ldg((const uint4*)(xt +
            (((size_t)(p3 >> 16)) * NN + (size_t)(p3 & 0xFFFFu)) * DO) + lane);
        acc_vec(acc, v0); acc_vec(acc, v1); acc_vec(acc, v2); acc_vec(acc, v3);
    }
    for (; j < e; j++) {
        uint32_t p0 = perm[j];
        uint4 v0 = __ldg((const uint4*)(xt +
            (((size_t)(p0 >> 16)) * NN + (size_t)(p0 & 0xFFFFu)) * DO) + lane);
        acc_vec(acc, v0);
    }

    const float4 b0 = *(const float4*)(bias + lane * 8);
    const float4 b1 = *(const float4*)(bias + lane * 8 + 4);
    float4 o0, o1;
    o0.x = fmaxf(acc[0] + b0.x, 0.f); o0.y = fmaxf(acc[1] + b0.y, 0.f);
    o0.z = fmaxf(acc[2] + b0.z, 0.f); o0.w = fmaxf(acc[3] + b0.w, 0.f);
    o1.x = fmaxf(acc[4] + b1.x, 0.f); o1.y = fmaxf(acc[5] + b1.y, 0.f);
    o1.z = fmaxf(acc[6] + b1.z, 0.f); o1.w = fmaxf(acc[7] + b1.w, 0.f);

    float* dst = out + (size_t)n * DO + lane * 8;
    *(float4*)dst = o0;
    *(float4*)(dst + 4) = o1;
}

extern "C" void kernel_launch(void* const* d_in, const int* in_sizes, int n_in,
                              void* d_out, int out_size) {
    const float* x          = (const float*)d_in[0];
    const int*   edge_index = (const int*)d_in[1];
    const int*   edge_type  = (const int*)d_in[2];
    const float* weight     = (const float*)d_in[3];
    const float* bias       = (const float*)d_in[4];
    float* out = (float*)d_out;

    __half *xh, *wh, *xt;
    int *cnt, *offs, *curs, *bsum, *bbase;
    uint32_t* perm;
    cudaGetSymbolAddress((void**)&xh, g_xh);
    cudaGetSymbolAddress((void**)&wh, g_wh);
    cudaGetSymbolAddress((void**)&xt, g_xt);
    cudaGetSymbolAddress((void**)&cnt, g_cnt);
    cudaGetSymbolAddress((void**)&offs, g_offs);
    cudaGetSymbolAddress((void**)&curs, g_curs);
    cudaGetSymbolAddress((void**)&bsum, g_bsum);
    cudaGetSymbolAddress((void**)&bbase, g_bbase);
    cudaGetSymbolAddress((void**)&perm, g_perm);

    cudaFuncSetAttribute(rgcn_gemm, cudaFuncAttributeMaxDynamicSharedMemorySize, SMEM_DYN);

    const int xn4 = NN * DI / 4;
    const int wn4 = NR * DI * DO / 4;
    rgcn_tohalf<<<(xn4 + 255) / 256, 256>>>((const float4*)x, (half2*)xh, xn4);
    rgcn_tohalf<<<(wn4 + 255) / 256, 256>>>((const float4*)weight, (half2*)wh, wn4);

    // CSR build
    cudaMemsetAsync(cnt, 0, NN * sizeof(int));
    rgcn_count<<<(NE + 255) / 256, 256>>>(edge_index, cnt);
    rgcn_scanA<<<NBLK, 256>>>(cnt, offs, bsum);
    rgcn_scanB<<<1, 256>>>(bsum, bbase);
    rgcn_scanC<<<NBLK, 256>>>(offs, bbase, curs);
    rgcn_fill<<<(NE + 255) / 256, 256>>>(edge_index, edge_type, curs, perm);

    dim3 gg((NN + 127) / 128, DO / 128, NR);     // 391 x 2 x 8
    rgcn_gemm<<<gg, 128, SMEM_DYN>>>(xh, wh, xt);

    rgcn_aggregate<<<(NN + 7) / 8, 256>>>(xt, bias, offs, perm, out);
}